// round 1
// baseline (speedup 1.0000x reference)
#include <cuda_runtime.h>
#include <math.h>

#define BSZ 8192
#define KN  32
#define DD  512

// Device scratch (static globals: allocation-free per harness rules)
__device__ float g_M[DD * DD];      // w1^T @ w2
__device__ float g_c[DD];           // b1 @ w2
__device__ float g_u[DD];           // b2 @ w1
__device__ float g_s0;              // b1 . b2
__device__ float g_q2[BSZ * DD];    // x @ M + c

// ---------------------------------------------------------------------------
// Kernel 1: M[j][d] = sum_e w1[e][j] * w2[e][d]   (512x512, 134M FMA)
// ---------------------------------------------------------------------------
__global__ void precompute_M(const float* __restrict__ w1,
                             const float* __restrict__ w2) {
    __shared__ float s1[32][33];
    __shared__ float s2[32][33];
    int tx = threadIdx.x, ty = threadIdx.y;
    int j0 = blockIdx.x * 32, d0 = blockIdx.y * 32;
    float acc = 0.f;
    for (int e0 = 0; e0 < DD; e0 += 32) {
        s1[ty][tx] = w1[(e0 + ty) * DD + j0 + tx];   // s1[e_loc][j_loc]
        s2[ty][tx] = w2[(e0 + ty) * DD + d0 + tx];   // s2[e_loc][d_loc]
        __syncthreads();
#pragma unroll
        for (int e = 0; e < 32; e++) acc += s1[e][ty] * s2[e][tx];
        __syncthreads();
    }
    g_M[(j0 + ty) * DD + d0 + tx] = acc;
}

// ---------------------------------------------------------------------------
// Kernel 2: c[d] = sum_e b1[e]*w2[e][d];  u[d] = sum_e b2[e]*w1[e][d];  s0
// ---------------------------------------------------------------------------
__global__ void precompute_vec(const float* __restrict__ w1,
                               const float* __restrict__ w2,
                               const float* __restrict__ b1,
                               const float* __restrict__ b2) {
    int d = threadIdx.x;  // 512 threads
    float c = 0.f, u = 0.f;
    for (int e = 0; e < DD; e++) {
        c += b1[e] * w2[e * DD + d];
        u += b2[e] * w1[e * DD + d];
    }
    g_c[d] = c;
    g_u[d] = u;
    __shared__ float red[DD];
    red[d] = b1[d] * b2[d];
    __syncthreads();
    for (int s = DD / 2; s > 0; s >>= 1) {
        if (d < s) red[d] += red[d + s];
        __syncthreads();
    }
    if (d == 0) g_s0 = red[0];
}

// ---------------------------------------------------------------------------
// Kernel 3: q2 = x @ M + c    [8192,512] x [512,512]  (2.1 G FMA)
// Classic 128x128x8 register-blocked SGEMM, 256 threads, 8x8 per thread.
// ---------------------------------------------------------------------------
__global__ __launch_bounds__(256) void gemm_q2(const float* __restrict__ A) {
    const int BM = 128, BN = 128, BK = 8;
    __shared__ float As[BK][BM];   // transposed A tile
    __shared__ float Bs[BK][BN];

    int bx = blockIdx.x;  // N tiles: 4
    int by = blockIdx.y;  // M tiles: 64
    int tid = threadIdx.x;

    // A tile load mapping: 128 rows x 8 cols = 256 float4
    int arow  = tid >> 1;          // 0..127
    int acol4 = (tid & 1) * 4;     // 0 or 4
    // B tile load mapping: 8 rows x 128 cols = 256 float4
    int brow  = tid >> 5;          // 0..7
    int bcol4 = (tid & 31) * 4;

    int trow = (tid >> 4) * 8;     // 0..120
    int tcol = (tid & 15) * 8;     // 0..120

    float acc[8][8];
#pragma unroll
    for (int i = 0; i < 8; i++)
#pragma unroll
        for (int j = 0; j < 8; j++) acc[i][j] = 0.f;

    const float* Aptr = A + (size_t)(by * BM + arow) * DD + acol4;
    const float* Bptr = g_M + brow * DD + bx * BN + bcol4;

    for (int k0 = 0; k0 < DD; k0 += BK) {
        float4 av = *(const float4*)(Aptr + k0);
        As[acol4 + 0][arow] = av.x;
        As[acol4 + 1][arow] = av.y;
        As[acol4 + 2][arow] = av.z;
        As[acol4 + 3][arow] = av.w;
        float4 bv = *(const float4*)(Bptr + (size_t)k0 * DD);
        *(float4*)&Bs[brow][bcol4] = bv;
        __syncthreads();
#pragma unroll
        for (int k = 0; k < BK; k++) {
            float4 a0 = *(const float4*)&As[k][trow];
            float4 a1 = *(const float4*)&As[k][trow + 4];
            float4 b0 = *(const float4*)&Bs[k][tcol];
            float4 b1v = *(const float4*)&Bs[k][tcol + 4];
            float ar[8] = {a0.x, a0.y, a0.z, a0.w, a1.x, a1.y, a1.z, a1.w};
            float br[8] = {b0.x, b0.y, b0.z, b0.w, b1v.x, b1v.y, b1v.z, b1v.w};
#pragma unroll
            for (int i = 0; i < 8; i++)
#pragma unroll
                for (int j = 0; j < 8; j++) acc[i][j] += ar[i] * br[j];
        }
        __syncthreads();
    }

    // Epilogue: add bias c, store q2
#pragma unroll
    for (int i = 0; i < 8; i++) {
        int r = by * BM + trow + i;
#pragma unroll
        for (int j = 0; j < 8; j += 4) {
            float4 cv = *(const float4*)&g_c[bx * BN + tcol + j];
            float4 o;
            o.x = acc[i][j + 0] + cv.x;
            o.y = acc[i][j + 1] + cv.y;
            o.z = acc[i][j + 2] + cv.z;
            o.w = acc[i][j + 3] + cv.w;
            *(float4*)&g_q2[(size_t)r * DD + bx * BN + tcol + j] = o;
        }
    }
}

// ---------------------------------------------------------------------------
// Kernel 4: one warp per row b.
//   qb   = x_b . u + s0
//   s_k  = (q2_b . keys_bk + qb) / sqrt(512)    (lane k holds s_k)
//   a    = softmax(s)
//   out  = 0.5*x + 0.5 * sum_k a_k * values_bk
// Streams keys + values exactly once: ~1 GB -> HBM-bound.
// ---------------------------------------------------------------------------
__global__ __launch_bounds__(256) void attend(const float* __restrict__ x,
                                              const float* __restrict__ keys,
                                              const float* __restrict__ values,
                                              float* __restrict__ out) {
    int warp = (blockIdx.x * blockDim.x + threadIdx.x) >> 5;
    int lane = threadIdx.x & 31;
    if (warp >= BSZ) return;

    const float4* xr  = (const float4*)(x + (size_t)warp * DD);
    const float4* q2r = (const float4*)(g_q2 + (size_t)warp * DD);
    const float4* kb  = (const float4*)(keys + (size_t)warp * KN * DD);
    const float4* vb  = (const float4*)(values + (size_t)warp * KN * DD);
    const float4* ur  = (const float4*)g_u;

    float4 xv[4], qv[4];
#pragma unroll
    for (int i = 0; i < 4; i++) {
        xv[i] = xr[lane + 32 * i];
        qv[i] = q2r[lane + 32 * i];
    }

    // qb = x . u + s0  (butterfly reduce so every lane has it)
    float qb = 0.f;
#pragma unroll
    for (int i = 0; i < 4; i++) {
        float4 uv = ur[lane + 32 * i];
        qb += xv[i].x * uv.x + xv[i].y * uv.y + xv[i].z * uv.z + xv[i].w * uv.w;
    }
#pragma unroll
    for (int o = 16; o > 0; o >>= 1) qb += __shfl_xor_sync(0xFFFFFFFFu, qb, o);
    qb += g_s0;

    const float scale = 0.044194173824159216f;  // 1/sqrt(512)

    // Pass 1: scores. Software-pipelined loads for MLP.
    float myscore = 0.f;
    float4 cur[4];
#pragma unroll
    for (int i = 0; i < 4; i++) cur[i] = kb[lane + 32 * i];

#pragma unroll
    for (int k = 0; k < KN; k++) {
        float4 nxt[4];
        if (k + 1 < KN) {
#pragma unroll
            for (int i = 0; i < 4; i++) nxt[i] = kb[(k + 1) * 128 + lane + 32 * i];
        }
        float p = 0.f;
#pragma unroll
        for (int i = 0; i < 4; i++) {
            p += qv[i].x * cur[i].x + qv[i].y * cur[i].y +
                 qv[i].z * cur[i].z + qv[i].w * cur[i].w;
        }
#pragma unroll
        for (int o = 16; o > 0; o >>= 1) p += __shfl_xor_sync(0xFFFFFFFFu, p, o);
        float s = (p + qb) * scale;
        if (lane == k) myscore = s;
#pragma unroll
        for (int i = 0; i < 4; i++) cur[i] = nxt[i];
    }

    // Softmax across lanes (K == 32 == warp size)
    float m = myscore;
#pragma unroll
    for (int o = 16; o > 0; o >>= 1)
        m = fmaxf(m, __shfl_xor_sync(0xFFFFFFFFu, m, o));
    float e = expf(myscore - m);
    float sum = e;
#pragma unroll
    for (int o = 16; o > 0; o >>= 1) sum += __shfl_xor_sync(0xFFFFFFFFu, sum, o);
    float a = e / sum;

    // Pass 2: combined = sum_k a_k * values_k
    float4 acc[4];
#pragma unroll
    for (int i = 0; i < 4; i++) acc[i] = make_float4(0.f, 0.f, 0.f, 0.f);

#pragma unroll
    for (int k = 0; k < KN; k++) {
        float w = __shfl_sync(0xFFFFFFFFu, a, k);
#pragma unroll
        for (int i = 0; i < 4; i++) {
            float4 vv = vb[k * 128 + lane + 32 * i];
            acc[i].x += w * vv.x;
            acc[i].y += w * vv.y;
            acc[i].z += w * vv.z;
            acc[i].w += w * vv.w;
        }
    }

    // out = 0.5*x + 0.5*combined
    float4* outr = (float4*)(out + (size_t)warp * DD);
#pragma unroll
    for (int i = 0; i < 4; i++) {
        float4 o;
        o.x = 0.5f * xv[i].x + 0.5f * acc[i].x;
        o.y = 0.5f * xv[i].y + 0.5f * acc[i].y;
        o.z = 0.5f * xv[i].z + 0.5f * acc[i].z;
        o.w = 0.5f * xv[i].w + 0.5f * acc[i].w;
        outr[lane + 32 * i] = o;
    }
}

// ---------------------------------------------------------------------------
extern "C" void kernel_launch(void* const* d_in, const int* in_sizes, int n_in,
                              void* d_out, int out_size) {
    const float* x      = (const float*)d_in[0];
    const float* keys   = (const float*)d_in[1];
    const float* values = (const float*)d_in[2];
    const float* w1     = (const float*)d_in[3];
    const float* b1     = (const float*)d_in[4];
    const float* w2     = (const float*)d_in[5];
    const float* b2     = (const float*)d_in[6];
    float* out = (float*)d_out;

    precompute_M<<<dim3(16, 16), dim3(32, 32)>>>(w1, w2);
    precompute_vec<<<1, 512>>>(w1, w2, b1, b2);
    gemm_q2<<<dim3(4, 64), 256>>>(x);
    attend<<<(BSZ * 32) / 256, 256>>>(x, keys, values, out);
}

// round 3
// speedup vs baseline: 1.1436x; 1.1436x over previous
#include <cuda_runtime.h>
#include <cuda_bf16.h>
#include <math.h>
#include <stdint.h>

#define BSZ 8192
#define KN  32
#define DD  512

// ---------------------------------------------------------------------------
// Device scratch
// ---------------------------------------------------------------------------
__device__ __nv_bfloat16 g_xh[BSZ * DD];
__device__ __nv_bfloat16 g_xl[BSZ * DD];
__device__ float g_Mt[DD * DD];            // Mt[d][j] = M[j][d] = sum_e w1[e][j] w2[e][d]
__device__ __nv_bfloat16 g_Mth[DD * DD];   // bf16 hi of Mt
__device__ __nv_bfloat16 g_Mtl[DD * DD];   // bf16 lo
__device__ float g_q2[BSZ * DD];           // x @ M + c
__device__ float g_c[DD];                  // b1 @ w2
__device__ float g_u[DD];                  // b2 @ w1
__device__ float g_s0;                     // b1 . b2

// ---------------------------------------------------------------------------
// Helpers
// ---------------------------------------------------------------------------
__device__ __forceinline__ uint32_t smem_u32(const void* p) {
    uint32_t a;
    asm("{ .reg .u64 t; cvta.to.shared.u64 t, %1; cvt.u32.u64 %0, t; }"
        : "=r"(a) : "l"(p));
    return a;
}
__device__ __forceinline__ void cp16(uint32_t saddr, const void* g) {
    asm volatile("cp.async.cg.shared.global [%0], [%1], 16;"
                 :: "r"(saddr), "l"(g));
}
__device__ __forceinline__ void ldsm4(uint32_t* r, uint32_t addr) {
    asm volatile("ldmatrix.sync.aligned.m8n8.x4.shared.b16 {%0,%1,%2,%3}, [%4];"
                 : "=r"(r[0]), "=r"(r[1]), "=r"(r[2]), "=r"(r[3]) : "r"(addr));
}
__device__ __forceinline__ void mma16816(float* c, const uint32_t* a,
                                         uint32_t b0, uint32_t b1) {
    asm volatile(
        "mma.sync.aligned.m16n8k16.row.col.f32.bf16.bf16.f32 "
        "{%0,%1,%2,%3}, {%4,%5,%6,%7}, {%8,%9}, {%0,%1,%2,%3};"
        : "+f"(c[0]), "+f"(c[1]), "+f"(c[2]), "+f"(c[3])
        : "r"(a[0]), "r"(a[1]), "r"(a[2]), "r"(a[3]), "r"(b0), "r"(b1));
}

// ---------------------------------------------------------------------------
// Mt[d][j] = sum_e w1[e][j] * w2[e][d]  (transposed store, coalesced)
// ---------------------------------------------------------------------------
__global__ void precompute_M(const float* __restrict__ w1,
                             const float* __restrict__ w2) {
    __shared__ float s1[32][33];
    __shared__ float s2[32][33];
    int tx = threadIdx.x, ty = threadIdx.y;
    int j0 = blockIdx.x * 32, d0 = blockIdx.y * 32;
    float acc = 0.f;
    for (int e0 = 0; e0 < DD; e0 += 32) {
        s1[ty][tx] = w1[(e0 + ty) * DD + j0 + tx];
        s2[ty][tx] = w2[(e0 + ty) * DD + d0 + tx];
        __syncthreads();
#pragma unroll
        for (int e = 0; e < 32; e++) acc += s1[e][tx] * s2[e][ty];
        __syncthreads();
    }
    g_Mt[(d0 + ty) * DD + j0 + tx] = acc;   // Mt[d][j]
}

// ---------------------------------------------------------------------------
// Elementwise bf16 split (vectorized)
// ---------------------------------------------------------------------------
__global__ void split_pair(const float* __restrict__ src,
                           __nv_bfloat16* __restrict__ h,
                           __nv_bfloat16* __restrict__ l, int n4) {
    int i = blockIdx.x * blockDim.x + threadIdx.x;
    if (i >= n4) return;
    float4 v = ((const float4*)src)[i];
    __nv_bfloat162 h01 = __floats2bfloat162_rn(v.x, v.y);
    __nv_bfloat162 h23 = __floats2bfloat162_rn(v.z, v.w);
    __nv_bfloat162 l01 = __floats2bfloat162_rn(v.x - __bfloat162float(h01.x),
                                               v.y - __bfloat162float(h01.y));
    __nv_bfloat162 l23 = __floats2bfloat162_rn(v.z - __bfloat162float(h23.x),
                                               v.w - __bfloat162float(h23.y));
    union { __nv_bfloat162 b[2]; uint2 u; } ph, pl;
    ph.b[0] = h01; ph.b[1] = h23;
    pl.b[0] = l01; pl.b[1] = l23;
    ((uint2*)h)[i] = ph.u;
    ((uint2*)l)[i] = pl.u;
}

// ---------------------------------------------------------------------------
// c[d] = b1 @ w2[:,d];  u[d] = b2 @ w1[:,d];  s0 = b1.b2   (8 blocks x 64)
// ---------------------------------------------------------------------------
__global__ void precompute_vec(const float* __restrict__ w1,
                               const float* __restrict__ w2,
                               const float* __restrict__ b1,
                               const float* __restrict__ b2) {
    __shared__ float b1s[DD], b2s[DD];
    __shared__ float red[64];
    int t = threadIdx.x;
    for (int i = t; i < DD; i += 64) { b1s[i] = b1[i]; b2s[i] = b2[i]; }
    __syncthreads();
    int d = blockIdx.x * 64 + t;
    float c = 0.f, u = 0.f;
#pragma unroll 4
    for (int e = 0; e < DD; e++) {
        c += b1s[e] * w2[e * DD + d];
        u += b2s[e] * w1[e * DD + d];
    }
    g_c[d] = c;
    g_u[d] = u;
    if (blockIdx.x == 0) {
        float s = 0.f;
        for (int i = t; i < DD; i += 64) s += b1s[i] * b2s[i];
        red[t] = s;
        __syncthreads();
        if (t < 32) {
            float v = red[t] + red[t + 32];
#pragma unroll
            for (int o = 16; o > 0; o >>= 1) v += __shfl_xor_sync(0xFFFFFFFFu, v, o);
            if (t == 0) g_s0 = v;
        }
    }
}

// ---------------------------------------------------------------------------
// bf16x3 GEMM via mma.sync (HMMA):
//   q2[8192,512] = [xh|xh|xl] @ [Mh;Ml;Mh] + c     (K' = 1536)
// Block tile 128x256, k-step 32, 8 warps (2m x 4n), warp tile 64x64.
// cp.async double buffer; ldmatrix fragments; 80B-padded smem rows.
// ---------------------------------------------------------------------------
#define NKT 48                       // 1536 / 32
#define STAGE_STRIDE 30720           // A(10240) + B(20480)
#define GSMEM_TOTAL (2 * STAGE_STRIDE + 1024)

__global__ __launch_bounds__(256) void gemm_mma(
    const __nv_bfloat16* __restrict__ xh, const __nv_bfloat16* __restrict__ xl,
    const __nv_bfloat16* __restrict__ Mth, const __nv_bfloat16* __restrict__ Mtl,
    float* __restrict__ outf) {
    extern __shared__ char smem[];
    uint32_t sbase = smem_u32(smem);
    int tid = threadIdx.x;
    int lane = tid & 31;
    int warp = tid >> 5;
    int wm = warp >> 2;            // 0..1
    int wn = warp & 3;             // 0..3
    int bx = blockIdx.x, by = blockIdx.y;

    // bias slice into smem (region after the two stages)
    float* sb = (float*)(smem + 2 * STAGE_STRIDE);
    sb[tid] = g_c[bx * 256 + tid];

    float acc[4][8][4];
#pragma unroll
    for (int i = 0; i < 4; i++)
#pragma unroll
        for (int n = 0; n < 8; n++)
#pragma unroll
            for (int q = 0; q < 4; q++) acc[i][n][q] = 0.f;

    // fragment lane addressing
    int arow  = lane & 15;
    int acol8 = (lane >> 4) * 8;                       // 0 or 8
    int brow  = (lane & 7) + ((lane >> 4) << 3);       // 0..15
    int bcol8 = ((lane >> 3) & 1) * 8;                 // 0 or 8

    auto load_stage = [&](int stage, int kt) {
        int pass = kt >> 4;
        const __nv_bfloat16* Asrc = (pass == 2) ? xl : xh;
        const __nv_bfloat16* Bsrc = (pass == 1) ? Mtl : Mth;
        int kk = (kt & 15) * 32;
        uint32_t abase = sbase + stage * STAGE_STRIDE;
        uint32_t bbase = abase + 10240;
#pragma unroll
        for (int i = 0; i < 2; i++) {
            int c = tid + 256 * i;
            int r = c >> 2, kc = (c & 3) * 8;
            cp16(abase + r * 80 + kc * 2,
                 Asrc + (size_t)(by * 128 + r) * DD + kk + kc);
        }
#pragma unroll
        for (int i = 0; i < 4; i++) {
            int c = tid + 256 * i;
            int n = c >> 2, kc = (c & 3) * 8;
            cp16(bbase + n * 80 + kc * 2,
                 Bsrc + (size_t)(bx * 256 + n) * DD + kk + kc);
        }
        asm volatile("cp.async.commit_group;" ::: "memory");
    };

    load_stage(0, 0);

#pragma unroll 1
    for (int kt = 0; kt < NKT; kt++) {
        int cur = kt & 1;
        if (kt + 1 < NKT) {
            load_stage(cur ^ 1, kt + 1);
            asm volatile("cp.async.wait_group 1;" ::: "memory");
        } else {
            asm volatile("cp.async.wait_group 0;" ::: "memory");
        }
        __syncthreads();

        uint32_t abase = sbase + cur * STAGE_STRIDE;
        uint32_t bbase = abase + 10240;
#pragma unroll
        for (int h = 0; h < 2; h++) {
            uint32_t af[4][4];
#pragma unroll
            for (int i = 0; i < 4; i++)
                ldsm4(af[i], abase + (uint32_t)(wm * 64 + i * 16 + arow) * 80 +
                                 (uint32_t)(h * 16 + acol8) * 2);
            uint32_t bf[4][4];
#pragma unroll
            for (int j = 0; j < 4; j++)
                ldsm4(bf[j], bbase + (uint32_t)(wn * 64 + j * 16 + brow) * 80 +
                                 (uint32_t)(h * 16 + bcol8) * 2);
#pragma unroll
            for (int i = 0; i < 4; i++)
#pragma unroll
                for (int j = 0; j < 4; j++) {
                    mma16816(acc[i][2 * j],     af[i], bf[j][0], bf[j][1]);
                    mma16816(acc[i][2 * j + 1], af[i], bf[j][2], bf[j][3]);
                }
        }
        __syncthreads();
    }

    // epilogue: add bias, store fp32
    int g = lane >> 2, t4 = lane & 3;
#pragma unroll
    for (int i = 0; i < 4; i++) {
        int r0 = by * 128 + wm * 64 + i * 16 + g;
#pragma unroll
        for (int n = 0; n < 8; n++) {
            int coll = wn * 64 + n * 8 + 2 * t4;
            int colg = bx * 256 + coll;
            float bx0 = sb[coll], bx1 = sb[coll + 1];
            float2 v0 = make_float2(acc[i][n][0] + bx0, acc[i][n][1] + bx1);
            float2 v1 = make_float2(acc[i][n][2] + bx0, acc[i][n][3] + bx1);
            *(float2*)(outf + (size_t)r0 * DD + colg) = v0;
            *(float2*)(outf + (size_t)(r0 + 8) * DD + colg) = v1;
        }
    }
}

// ---------------------------------------------------------------------------
// Attend (unchanged): one warp per row, streams keys+values once. 80% DRAM.
// ---------------------------------------------------------------------------
__global__ __launch_bounds__(256) void attend(const float* __restrict__ x,
                                              const float* __restrict__ keys,
                                              const float* __restrict__ values,
                                              float* __restrict__ out) {
    int warp = (blockIdx.x * blockDim.x + threadIdx.x) >> 5;
    int lane = threadIdx.x & 31;
    if (warp >= BSZ) return;

    const float4* xr  = (const float4*)(x + (size_t)warp * DD);
    const float4* q2r = (const float4*)(g_q2 + (size_t)warp * DD);
    const float4* kb  = (const float4*)(keys + (size_t)warp * KN * DD);
    const float4* vb  = (const float4*)(values + (size_t)warp * KN * DD);
    const float4* ur  = (const float4*)g_u;

    float4 xv[4], qv[4];
#pragma unroll
    for (int i = 0; i < 4; i++) {
        xv[i] = xr[lane + 32 * i];
        qv[i] = q2r[lane + 32 * i];
    }

    float qb = 0.f;
#pragma unroll
    for (int i = 0; i < 4; i++) {
        float4 uv = ur[lane + 32 * i];
        qb += xv[i].x * uv.x + xv[i].y * uv.y + xv[i].z * uv.z + xv[i].w * uv.w;
    }
#pragma unroll
    for (int o = 16; o > 0; o >>= 1) qb += __shfl_xor_sync(0xFFFFFFFFu, qb, o);
    qb += g_s0;

    const float scale = 0.044194173824159216f;  // 1/sqrt(512)

    float myscore = 0.f;
    float4 cur[4];
#pragma unroll
    for (int i = 0; i < 4; i++) cur[i] = kb[lane + 32 * i];

#pragma unroll
    for (int k = 0; k < KN; k++) {
        float4 nxt[4];
        if (k + 1 < KN) {
#pragma unroll
            for (int i = 0; i < 4; i++) nxt[i] = kb[(k + 1) * 128 + lane + 32 * i];
        }
        float p = 0.f;
#pragma unroll
        for (int i = 0; i < 4; i++) {
            p += qv[i].x * cur[i].x + qv[i].y * cur[i].y +
                 qv[i].z * cur[i].z + qv[i].w * cur[i].w;
        }
#pragma unroll
        for (int o = 16; o > 0; o >>= 1) p += __shfl_xor_sync(0xFFFFFFFFu, p, o);
        float s = (p + qb) * scale;
        if (lane == k) myscore = s;
#pragma unroll
        for (int i = 0; i < 4; i++) cur[i] = nxt[i];
    }

    float m = myscore;
#pragma unroll
    for (int o = 16; o > 0; o >>= 1)
        m = fmaxf(m, __shfl_xor_sync(0xFFFFFFFFu, m, o));
    float e = expf(myscore - m);
    float sum = e;
#pragma unroll
    for (int o = 16; o > 0; o >>= 1) sum += __shfl_xor_sync(0xFFFFFFFFu, sum, o);
    float a = e / sum;

    float4 acc[4];
#pragma unroll
    for (int i = 0; i < 4; i++) acc[i] = make_float4(0.f, 0.f, 0.f, 0.f);

#pragma unroll
    for (int k = 0; k < KN; k++) {
        float w = __shfl_sync(0xFFFFFFFFu, a, k);
#pragma unroll
        for (int i = 0; i < 4; i++) {
            float4 vv = vb[k * 128 + lane + 32 * i];
            acc[i].x += w * vv.x;
            acc[i].y += w * vv.y;
            acc[i].z += w * vv.z;
            acc[i].w += w * vv.w;
        }
    }

    float4* outr = (float4*)(out + (size_t)warp * DD);
#pragma unroll
    for (int i = 0; i < 4; i++) {
        float4 o;
        o.x = 0.5f * xv[i].x + 0.5f * acc[i].x;
        o.y = 0.5f * xv[i].y + 0.5f * acc[i].y;
        o.z = 0.5f * xv[i].z + 0.5f * acc[i].z;
        o.w = 0.5f * xv[i].w + 0.5f * acc[i].w;
        outr[lane + 32 * i] = o;
    }
}

// ---------------------------------------------------------------------------
extern "C" void kernel_launch(void* const* d_in, const int* in_sizes, int n_in,
                              void* d_out, int out_size) {
    const float* x      = (const float*)d_in[0];
    const float* keys   = (const float*)d_in[1];
    const float* values = (const float*)d_in[2];
    const float* w1     = (const float*)d_in[3];
    const float* b1     = (const float*)d_in[4];
    const float* w2     = (const float*)d_in[5];
    const float* b2     = (const float*)d_in[6];
    float* out = (float*)d_out;

    static int init_done = 0;
    if (!init_done) {
        cudaFuncSetAttribute(gemm_mma, cudaFuncAttributeMaxDynamicSharedMemorySize,
                             GSMEM_TOTAL);
        init_done = 1;
    }

    __nv_bfloat16 *xh, *xl, *Mth, *Mtl;
    float *Mt, *q2;
    cudaGetSymbolAddress((void**)&xh, g_xh);
    cudaGetSymbolAddress((void**)&xl, g_xl);
    cudaGetSymbolAddress((void**)&Mt, g_Mt);
    cudaGetSymbolAddress((void**)&Mth, g_Mth);
    cudaGetSymbolAddress((void**)&Mtl, g_Mtl);
    cudaGetSymbolAddress((void**)&q2, g_q2);

    precompute_M<<<dim3(16, 16), dim3(32, 32)>>>(w1, w2);
    precompute_vec<<<8, 64>>>(w1, w2, b1, b2);
    split_pair<<<(BSZ * DD / 4 + 255) / 256, 256>>>(x, xh, xl, BSZ * DD / 4);
    split_pair<<<(DD * DD / 4 + 255) / 256, 256>>>(Mt, Mth, Mtl, DD * DD / 4);

    gemm_mma<<<dim3(2, 64), 256, GSMEM_TOTAL>>>(xh, xl, Mth, Mtl, q2);

    attend<<<(BSZ * 32) / 256, 256>>>(x, keys, values, out);
}

// round 4
// speedup vs baseline: 1.4313x; 1.2516x over previous
#include <cuda_runtime.h>
#include <cuda_bf16.h>
#include <math.h>
#include <stdint.h>

#define BSZ 8192
#define KN  32
#define DD  512

// ---------------------------------------------------------------------------
// Device scratch
// ---------------------------------------------------------------------------
__device__ __nv_bfloat16 g_Mth[DD * DD];   // bf16 hi of Mt[d][j] = sum_e w1[e][j] w2[e][d]
__device__ __nv_bfloat16 g_Mtl[DD * DD];   // bf16 lo
__device__ float g_q2[BSZ * DD];           // x @ M + c
__device__ float g_c[DD];                  // b1 @ w2
__device__ float g_u[DD];                  // b2 @ w1
__device__ float g_s0;                     // b1 . b2

// ---------------------------------------------------------------------------
// Helpers
// ---------------------------------------------------------------------------
__device__ __forceinline__ uint32_t smem_u32(const void* p) {
    uint32_t a;
    asm("{ .reg .u64 t; cvta.to.shared.u64 t, %1; cvt.u32.u64 %0, t; }"
        : "=r"(a) : "l"(p));
    return a;
}
__device__ __forceinline__ void cp16(uint32_t saddr, const void* g) {
    asm volatile("cp.async.cg.shared.global [%0], [%1], 16;"
                 :: "r"(saddr), "l"(g));
}
__device__ __forceinline__ void ldsm4(uint32_t* r, uint32_t addr) {
    asm volatile("ldmatrix.sync.aligned.m8n8.x4.shared.b16 {%0,%1,%2,%3}, [%4];"
                 : "=r"(r[0]), "=r"(r[1]), "=r"(r[2]), "=r"(r[3]) : "r"(addr));
}
__device__ __forceinline__ void mma16816(float* c, const uint32_t* a,
                                         uint32_t b0, uint32_t b1) {
    asm volatile(
        "mma.sync.aligned.m16n8k16.row.col.f32.bf16.bf16.f32 "
        "{%0,%1,%2,%3}, {%4,%5,%6,%7}, {%8,%9}, {%0,%1,%2,%3};"
        : "+f"(c[0]), "+f"(c[1]), "+f"(c[2]), "+f"(c[3])
        : "r"(a[0]), "r"(a[1]), "r"(a[2]), "r"(a[3]), "r"(b0), "r"(b1));
}

// ---------------------------------------------------------------------------
// Mt[d][j] = sum_e w1[e][j] * w2[e][d], split-stored as bf16 hi/lo
// ---------------------------------------------------------------------------
__global__ void precompute_M(const float* __restrict__ w1,
                             const float* __restrict__ w2) {
    __shared__ float s1[32][33];
    __shared__ float s2[32][33];
    int tx = threadIdx.x, ty = threadIdx.y;
    int j0 = blockIdx.x * 32, d0 = blockIdx.y * 32;
    float acc = 0.f;
    for (int e0 = 0; e0 < DD; e0 += 32) {
        s1[ty][tx] = w1[(e0 + ty) * DD + j0 + tx];
        s2[ty][tx] = w2[(e0 + ty) * DD + d0 + tx];
        __syncthreads();
#pragma unroll
        for (int e = 0; e < 32; e++) acc += s1[e][tx] * s2[e][ty];
        __syncthreads();
    }
    __nv_bfloat16 hv = __float2bfloat16(acc);
    __nv_bfloat16 lv = __float2bfloat16(acc - __bfloat162float(hv));
    g_Mth[(d0 + ty) * DD + j0 + tx] = hv;
    g_Mtl[(d0 + ty) * DD + j0 + tx] = lv;
}

// ---------------------------------------------------------------------------
// c[d] = b1 @ w2[:,d];  u[d] = b2 @ w1[:,d];  s0 = b1.b2
// Grid 16 x 256: block handles 32 columns, 8 k-slices of 64.
// ---------------------------------------------------------------------------
__global__ __launch_bounds__(256) void precompute_vec(
    const float* __restrict__ w1, const float* __restrict__ w2,
    const float* __restrict__ b1, const float* __restrict__ b2) {
    __shared__ float pc[8][32];
    __shared__ float pu[8][32];
    __shared__ float rs0[256];
    int t = threadIdx.x;
    int col = t & 31, sl = t >> 5;
    int d = blockIdx.x * 32 + col;
    float c = 0.f, u = 0.f;
#pragma unroll 4
    for (int e = sl * 64; e < sl * 64 + 64; e++) {
        c += b1[e] * w2[e * DD + d];
        u += b2[e] * w1[e * DD + d];
    }
    pc[sl][col] = c;
    pu[sl][col] = u;
    if (blockIdx.x == 0) {
        float s = b1[t] * b2[t] + b1[t + 256] * b2[t + 256];
        rs0[t] = s;
    }
    __syncthreads();
    if (t < 32) {
        float cc = 0.f, uu = 0.f;
#pragma unroll
        for (int s = 0; s < 8; s++) { cc += pc[s][t]; uu += pu[s][t]; }
        g_c[blockIdx.x * 32 + t] = cc;
        g_u[blockIdx.x * 32 + t] = uu;
    }
    if (blockIdx.x == 0 && t >= 32 && t < 64) {
        int i = t - 32;
        float v = rs0[i] + rs0[i + 32] + rs0[i + 64] + rs0[i + 96] +
                  rs0[i + 128] + rs0[i + 160] + rs0[i + 192] + rs0[i + 224];
#pragma unroll
        for (int o = 16; o > 0; o >>= 1) v += __shfl_xor_sync(0xFFFFFFFFu, v, o);
        if (i == 0) g_s0 = v;
    }
}

// ---------------------------------------------------------------------------
// Fused-split bf16x3 GEMM: q2 = x @ M + c over PHYSICAL K=512 (16 k32 tiles).
// Per tile: x loaded fp32 once -> (xh, xl) in regs -> smem; M hi/lo via
// cp.async. acc += xh*Mh + xh*Ml + xl*Mh.
// Block tile 128x256, 8 warps (2m x 4n), warp tile 64x64, 80B-padded rows.
// ---------------------------------------------------------------------------
#define NKT 16
// per-stage: xh 10240, xl 10240, Mh 20480, Ml 20480
#define XH_OFF 0
#define XL_OFF 10240
#define MH_OFF 20480
#define ML_OFF 40960
#define STAGE_STRIDE 61440
#define GSMEM_TOTAL (2 * STAGE_STRIDE + 1024)

__global__ __launch_bounds__(256) void gemm_fused(
    const float* __restrict__ x,
    const __nv_bfloat16* __restrict__ Mth, const __nv_bfloat16* __restrict__ Mtl,
    float* __restrict__ outf) {
    extern __shared__ char smem[];
    uint32_t sbase = smem_u32(smem);
    int tid = threadIdx.x;
    int lane = tid & 31;
    int warp = tid >> 5;
    int wm = warp >> 2;
    int wn = warp & 3;
    int bx = blockIdx.x, by = blockIdx.y;

    float* sb = (float*)(smem + 2 * STAGE_STRIDE);
    sb[tid] = g_c[bx * 256 + tid];

    float acc[4][8][4];
#pragma unroll
    for (int i = 0; i < 4; i++)
#pragma unroll
        for (int n = 0; n < 8; n++)
#pragma unroll
            for (int q = 0; q < 4; q++) acc[i][n][q] = 0.f;

    int arow  = lane & 15;
    int acol8 = (lane >> 4) * 8;
    int brow  = (lane & 7) + ((lane >> 4) << 3);
    int bcol8 = ((lane >> 3) & 1) * 8;

    // x load mapping: 128 rows x 8 uint4/row = 1024 -> 4 per thread
    int xr_ = tid >> 1;               // base row pair mapping: c = tid+256*i
    (void)xr_;

    // M load mapping: 256 rows x 4 chunks = 1024 -> 4 per thread (each of Mh, Ml)
    auto load_M = [&](int stage, int kt) {
        int kk = kt * 32;
        uint32_t mh = sbase + stage * STAGE_STRIDE + MH_OFF;
        uint32_t ml = sbase + stage * STAGE_STRIDE + ML_OFF;
#pragma unroll
        for (int i = 0; i < 4; i++) {
            int c = tid + 256 * i;
            int n = c >> 2, q = c & 3;
            cp16(mh + n * 80 + q * 16,
                 Mth + (size_t)(bx * 256 + n) * DD + kk + q * 8);
            cp16(ml + n * 80 + q * 16,
                 Mtl + (size_t)(bx * 256 + n) * DD + kk + q * 8);
        }
        asm volatile("cp.async.commit_group;" ::: "memory");
    };

    auto load_x_regs = [&](int kt, float4* vr) {
        int kk = kt * 32;
#pragma unroll
        for (int i = 0; i < 2; i++) {
            int c = tid + 256 * i;
            int r = c >> 2, q = c & 3;   // 128 rows x 4 float4 per row (32 floats)
            vr[i] = *(const float4*)(x + (size_t)(by * 128 + r) * DD + kk + q * 8);
            vr[i + 2] = *(const float4*)(x + (size_t)(by * 128 + r) * DD + kk + q * 8 + 4);
        }
    };

    auto store_x = [&](int stage, const float4* vr) {
        uint32_t xh = sbase + stage * STAGE_STRIDE + XH_OFF;
        uint32_t xl = sbase + stage * STAGE_STRIDE + XL_OFF;
#pragma unroll
        for (int i = 0; i < 2; i++) {
            int c = tid + 256 * i;
            int r = c >> 2, q = c & 3;
            float4 v0 = vr[i], v1 = vr[i + 2];
            __nv_bfloat162 h01 = __floats2bfloat162_rn(v0.x, v0.y);
            __nv_bfloat162 h23 = __floats2bfloat162_rn(v0.z, v0.w);
            __nv_bfloat162 h45 = __floats2bfloat162_rn(v1.x, v1.y);
            __nv_bfloat162 h67 = __floats2bfloat162_rn(v1.z, v1.w);
            __nv_bfloat162 l01 = __floats2bfloat162_rn(v0.x - __bfloat162float(h01.x),
                                                       v0.y - __bfloat162float(h01.y));
            __nv_bfloat162 l23 = __floats2bfloat162_rn(v0.z - __bfloat162float(h23.x),
                                                       v0.w - __bfloat162float(h23.y));
            __nv_bfloat162 l45 = __floats2bfloat162_rn(v1.x - __bfloat162float(h45.x),
                                                       v1.y - __bfloat162float(h45.y));
            __nv_bfloat162 l67 = __floats2bfloat162_rn(v1.z - __bfloat162float(h67.x),
                                                       v1.w - __bfloat162float(h67.y));
            union { __nv_bfloat162 b[4]; uint4 u; } ph, pl;
            ph.b[0] = h01; ph.b[1] = h23; ph.b[2] = h45; ph.b[3] = h67;
            pl.b[0] = l01; pl.b[1] = l23; pl.b[2] = l45; pl.b[3] = l67;
            *(uint4*)(smem + (xh - sbase) + r * 80 + q * 16) = ph.u;
            *(uint4*)(smem + (xl - sbase) + r * 80 + q * 16) = pl.u;
        }
    };

    // prologue: stage 0
    float4 xcur[4];
    load_x_regs(0, xcur);
    load_M(0, 0);
    store_x(0, xcur);

#pragma unroll 1
    for (int kt = 0; kt < NKT; kt++) {
        int cur = kt & 1;
        float4 xnext[4];
        if (kt + 1 < NKT) {
            load_x_regs(kt + 1, xnext);
            load_M(cur ^ 1, kt + 1);
            asm volatile("cp.async.wait_group 1;" ::: "memory");
        } else {
            asm volatile("cp.async.wait_group 0;" ::: "memory");
        }
        __syncthreads();

        uint32_t base = sbase + cur * STAGE_STRIDE;
#pragma unroll
        for (int h = 0; h < 2; h++) {
            uint32_t afh[4][4], afl[4][4];
#pragma unroll
            for (int i = 0; i < 4; i++) {
                uint32_t rowoff = (uint32_t)(wm * 64 + i * 16 + arow) * 80 +
                                  (uint32_t)(h * 16 + acol8) * 2;
                ldsm4(afh[i], base + XH_OFF + rowoff);
                ldsm4(afl[i], base + XL_OFF + rowoff);
            }
            uint32_t bfh[4][4], bfl[4][4];
#pragma unroll
            for (int j = 0; j < 4; j++) {
                uint32_t rowoff = (uint32_t)(wn * 64 + j * 16 + brow) * 80 +
                                  (uint32_t)(h * 16 + bcol8) * 2;
                ldsm4(bfh[j], base + MH_OFF + rowoff);
                ldsm4(bfl[j], base + ML_OFF + rowoff);
            }
#pragma unroll
            for (int i = 0; i < 4; i++)
#pragma unroll
                for (int j = 0; j < 4; j++) {
                    mma16816(acc[i][2 * j],     afh[i], bfh[j][0], bfh[j][1]);
                    mma16816(acc[i][2 * j + 1], afh[i], bfh[j][2], bfh[j][3]);
                    mma16816(acc[i][2 * j],     afh[i], bfl[j][0], bfl[j][1]);
                    mma16816(acc[i][2 * j + 1], afh[i], bfl[j][2], bfl[j][3]);
                    mma16816(acc[i][2 * j],     afl[i], bfh[j][0], bfh[j][1]);
                    mma16816(acc[i][2 * j + 1], afl[i], bfh[j][2], bfh[j][3]);
                }
        }
        if (kt + 1 < NKT) {
            store_x(cur ^ 1, xnext);
        }
        __syncthreads();
    }

    // epilogue
    int g = lane >> 2, t4 = lane & 3;
#pragma unroll
    for (int i = 0; i < 4; i++) {
        int r0 = by * 128 + wm * 64 + i * 16 + g;
#pragma unroll
        for (int n = 0; n < 8; n++) {
            int coll = wn * 64 + n * 8 + 2 * t4;
            int colg = bx * 256 + coll;
            float bx0 = sb[coll], bx1 = sb[coll + 1];
            float2 v0 = make_float2(acc[i][n][0] + bx0, acc[i][n][1] + bx1);
            float2 v1 = make_float2(acc[i][n][2] + bx0, acc[i][n][3] + bx1);
            *(float2*)(outf + (size_t)r0 * DD + colg) = v0;
            *(float2*)(outf + (size_t)(r0 + 8) * DD + colg) = v1;
        }
    }
}

// ---------------------------------------------------------------------------
// Attend (unchanged): one warp per row, streams keys+values once. 80% DRAM.
// ---------------------------------------------------------------------------
__global__ __launch_bounds__(256) void attend(const float* __restrict__ x,
                                              const float* __restrict__ keys,
                                              const float* __restrict__ values,
                                              float* __restrict__ out) {
    int warp = (blockIdx.x * blockDim.x + threadIdx.x) >> 5;
    int lane = threadIdx.x & 31;
    if (warp >= BSZ) return;

    const float4* xr  = (const float4*)(x + (size_t)warp * DD);
    const float4* q2r = (const float4*)(g_q2 + (size_t)warp * DD);
    const float4* kb  = (const float4*)(keys + (size_t)warp * KN * DD);
    const float4* vb  = (const float4*)(values + (size_t)warp * KN * DD);
    const float4* ur  = (const float4*)g_u;

    float4 xv[4], qv[4];
#pragma unroll
    for (int i = 0; i < 4; i++) {
        xv[i] = xr[lane + 32 * i];
        qv[i] = q2r[lane + 32 * i];
    }

    float qb = 0.f;
#pragma unroll
    for (int i = 0; i < 4; i++) {
        float4 uv = ur[lane + 32 * i];
        qb += xv[i].x * uv.x + xv[i].y * uv.y + xv[i].z * uv.z + xv[i].w * uv.w;
    }
#pragma unroll
    for (int o = 16; o > 0; o >>= 1) qb += __shfl_xor_sync(0xFFFFFFFFu, qb, o);
    qb += g_s0;

    const float scale = 0.044194173824159216f;  // 1/sqrt(512)

    float myscore = 0.f;
    float4 cur[4];
#pragma unroll
    for (int i = 0; i < 4; i++) cur[i] = kb[lane + 32 * i];

#pragma unroll
    for (int k = 0; k < KN; k++) {
        float4 nxt[4];
        if (k + 1 < KN) {
#pragma unroll
            for (int i = 0; i < 4; i++) nxt[i] = kb[(k + 1) * 128 + lane + 32 * i];
        }
        float p = 0.f;
#pragma unroll
        for (int i = 0; i < 4; i++) {
            p += qv[i].x * cur[i].x + qv[i].y * cur[i].y +
                 qv[i].z * cur[i].z + qv[i].w * cur[i].w;
        }
#pragma unroll
        for (int o = 16; o > 0; o >>= 1) p += __shfl_xor_sync(0xFFFFFFFFu, p, o);
        float s = (p + qb) * scale;
        if (lane == k) myscore = s;
#pragma unroll
        for (int i = 0; i < 4; i++) cur[i] = nxt[i];
    }

    float m = myscore;
#pragma unroll
    for (int o = 16; o > 0; o >>= 1)
        m = fmaxf(m, __shfl_xor_sync(0xFFFFFFFFu, m, o));
    float e = expf(myscore - m);
    float sum = e;
#pragma unroll
    for (int o = 16; o > 0; o >>= 1) sum += __shfl_xor_sync(0xFFFFFFFFu, sum, o);
    float a = e / sum;

    float4 acc[4];
#pragma unroll
    for (int i = 0; i < 4; i++) acc[i] = make_float4(0.f, 0.f, 0.f, 0.f);

#pragma unroll
    for (int k = 0; k < KN; k++) {
        float w = __shfl_sync(0xFFFFFFFFu, a, k);
#pragma unroll
        for (int i = 0; i < 4; i++) {
            float4 vv = vb[k * 128 + lane + 32 * i];
            acc[i].x += w * vv.x;
            acc[i].y += w * vv.y;
            acc[i].z += w * vv.z;
            acc[i].w += w * vv.w;
        }
    }

    float4* outr = (float4*)(out + (size_t)warp * DD);
#pragma unroll
    for (int i = 0; i < 4; i++) {
        float4 o;
        o.x = 0.5f * xv[i].x + 0.5f * acc[i].x;
        o.y = 0.5f * xv[i].y + 0.5f * acc[i].y;
        o.z = 0.5f * xv[i].z + 0.5f * acc[i].z;
        o.w = 0.5f * xv[i].w + 0.5f * acc[i].w;
        outr[lane + 32 * i] = o;
    }
}

// ---------------------------------------------------------------------------
extern "C" void kernel_launch(void* const* d_in, const int* in_sizes, int n_in,
                              void* d_out, int out_size) {
    const float* x      = (const float*)d_in[0];
    const float* keys   = (const float*)d_in[1];
    const float* values = (const float*)d_in[2];
    const float* w1     = (const float*)d_in[3];
    const float* b1     = (const float*)d_in[4];
    const float* w2     = (const float*)d_in[5];
    const float* b2     = (const float*)d_in[6];
    float* out = (float*)d_out;

    cudaFuncSetAttribute(gemm_fused, cudaFuncAttributeMaxDynamicSharedMemorySize,
                         GSMEM_TOTAL);

    __nv_bfloat16 *Mth, *Mtl;
    float *q2;
    cudaGetSymbolAddress((void**)&Mth, g_Mth);
    cudaGetSymbolAddress((void**)&Mtl, g_Mtl);
    cudaGetSymbolAddress((void**)&q2, g_q2);

    precompute_M<<<dim3(16, 16), dim3(32, 32)>>>(w1, w2);
    precompute_vec<<<16, 256>>>(w1, w2, b1, b2);
    gemm_fused<<<dim3(2, 64), 256, GSMEM_TOTAL>>>(x, Mth, Mtl, q2);
    attend<<<(BSZ * 32) / 256, 256>>>(x, keys, values, out);
}